// round 6
// baseline (speedup 1.0000x reference)
#include <cuda_runtime.h>
#include <math.h>

// Problem constants (match reference)
#define BB   16
#define CC   128
#define LL   16000
#define KK   256
#define SS   3937          // (L - K)/4 + 1
#define NITER 10
#define STEP 0.1f
#define THR  0.5f
#define NJ   4000          // recon phase length: L/4

// Scratch (no allocations allowed -> __device__ globals)
__device__ float g_drive[BB * CC * SS];   // ~32.25 MB
__device__ float g_u[BB * CC * SS];       // ~32.25 MB
__device__ float g_recon[BB * LL];        // 1 MB, single-rounded fp32 recon

__device__ __forceinline__ float hshrink(float u) {
    return (fabsf(u) > THR) ? u : 0.0f;
}

// Packed fp32x2 helpers (Blackwell). Each half is an IEEE fp32 FMA -> the
// per-element accumulation chains are bit-identical to scalar FFMA.
__device__ __forceinline__ unsigned long long splat2(float a) {
    unsigned long long r;
    asm("mov.b64 %0, {%1, %1};" : "=l"(r) : "f"(a));
    return r;
}
__device__ __forceinline__ void fma2(unsigned long long& acc,
                                     unsigned long long a,
                                     unsigned long long b) {
    asm("fma.rn.f32x2 %0, %1, %2, %0;" : "+l"(acc) : "l"(a), "l"(b));
}
__device__ __forceinline__ float2 unpack2(unsigned long long v) {
    float lo, hi;
    asm("mov.b64 {%0, %1}, %2;" : "=f"(lo), "=f"(hi) : "l"(v));
    return make_float2(lo, hi);
}

// ---------------------------------------------------------------------------
// k_conv: strided conv (stride 4, K=256), fp32, k-ascending serial FMA chains
// (verified anchor from R5 - unchanged). MODE 0: input = x, writes drive and
// u1 = 0.1f*drive. MODE 1: input = g_recon, fused LCA u-update.
// ---------------------------------------------------------------------------
template <int MODE>
__global__ __launch_bounds__(256) void k_conv(const float* __restrict__ xin,
                                              const float* __restrict__ Wg) {
    __shared__ float Ws[32 * KK];    // 32 KB
    __shared__ float xs[768];        // 3 KB

    const int stile = blockIdx.x;    // 0..30
    const int cb    = blockIdx.y;    // 0..3
    const int b     = blockIdx.z;    // 0..15
    const int s0    = stile * 128;
    const int c0    = cb * 32;
    const int tid   = threadIdx.x;

    const float4* Wg4 = (const float4*)(Wg + c0 * KK);
    float4* Ws4 = (float4*)Ws;
    #pragma unroll
    for (int i = tid; i < (32 * KK) / 4; i += 256) Ws4[i] = Wg4[i];

    {
        const float* src = (MODE == 0) ? (xin + b * LL) : (g_recon + b * LL);
        for (int i = tid; i < 768; i += 256) {
            int gt = 4 * s0 + i;
            xs[i] = (gt < LL) ? src[gt] : 0.0f;
        }
    }
    __syncthreads();

    const int lane = tid & 31;
    const int wg   = tid >> 5;

    float acc[4][4];
    #pragma unroll
    for (int i = 0; i < 4; i++)
        #pragma unroll
        for (int j = 0; j < 4; j++) acc[i][j] = 0.0f;

    const float* wrow = Ws + (wg * 4) * KK;

    #pragma unroll 4
    for (int k = 0; k < KK; k += 4) {
        float4 wv0 = *(const float4*)&wrow[0 * KK + k];
        float4 wv1 = *(const float4*)&wrow[1 * KK + k];
        float4 wv2 = *(const float4*)&wrow[2 * KK + k];
        float4 wv3 = *(const float4*)&wrow[3 * KK + k];
        #pragma unroll
        for (int m = 0; m < 4; m++) {
            float4 xv = *(const float4*)&xs[4 * lane + 128 * m + k];
            acc[0][m] += wv0.x * xv.x; acc[0][m] += wv0.y * xv.y;
            acc[0][m] += wv0.z * xv.z; acc[0][m] += wv0.w * xv.w;
            acc[1][m] += wv1.x * xv.x; acc[1][m] += wv1.y * xv.y;
            acc[1][m] += wv1.z * xv.z; acc[1][m] += wv1.w * xv.w;
            acc[2][m] += wv2.x * xv.x; acc[2][m] += wv2.y * xv.y;
            acc[2][m] += wv2.z * xv.z; acc[2][m] += wv2.w * xv.w;
            acc[3][m] += wv3.x * xv.x; acc[3][m] += wv3.y * xv.y;
            acc[3][m] += wv3.z * xv.z; acc[3][m] += wv3.w * xv.w;
        }
    }

    #pragma unroll
    for (int ci = 0; ci < 4; ci++) {
        const int c = c0 + wg * 4 + ci;
        #pragma unroll
        for (int m = 0; m < 4; m++) {
            const int s = s0 + lane + 32 * m;
            if (s < SS) {
                const int idx = (b * CC + c) * SS + s;
                if (MODE == 0) {
                    g_drive[idx] = acc[ci][m];
                    g_u[idx]     = STEP * acc[ci][m];
                } else {
                    float u = g_u[idx];
                    float a = hshrink(u);
                    float t = ((g_drive[idx] - u) - acc[ci][m]) + a;
                    g_u[idx] = fmaf(STEP, t, u);
                }
            }
        }
    }
}

// ---------------------------------------------------------------------------
// k_recon v2: same serial chain as the verified R5 kernel (c = 0..127
// ascending outer, d = 63..0 inner), three bit-exact optimizations:
//   1. packed fma.rn.f32x2 (phases r0r1 / r2r3 pair naturally from wv.128)
//   2. 2 j per thread (jA = j0+tid, jB = jA+128; both stride-1 windows)
//   3. skip channels whose whole a-window is zero (contributes exactly +0)
// CTA = (j-tile 256, batch), 128 threads; grid (16, 16).
// ---------------------------------------------------------------------------
__global__ __launch_bounds__(128) void k_recon(const float* __restrict__ Wg) {
    extern __shared__ float sm[];
    float* Ws = sm;                       // 32*256 floats (32 KB)
    float* As = sm + 32 * KK;             // 32*320 floats (40 KB)
    int* flags = (int*)(sm + 32 * KK + 32 * 320);   // 32 ints

    const int jt  = blockIdx.x;   // 0..15
    const int b   = blockIdx.y;   // 0..15
    const int j0  = jt * 256;
    const int tid = threadIdx.x;  // 0..127
    const int jA  = j0 + tid;
    const int jB  = jA + 128;

    unsigned long long accA0 = 0ULL, accA1 = 0ULL;   // (r0,r1), (r2,r3) of jA
    unsigned long long accB0 = 0ULL, accB1 = 0ULL;   // same for jB

    for (int cc = 0; cc < 4; cc++) {
        const int c0 = cc * 32;
        __syncthreads();               // previous chunk fully consumed
        if (tid < 32) flags[tid] = 0;
        __syncthreads();

        // W chunk [c0, c0+32)
        const float4* Wg4 = (const float4*)(Wg + c0 * KK);
        float4* Ws4 = (float4*)Ws;
        #pragma unroll
        for (int i = tid; i < (32 * KK) / 4; i += 128) Ws4[i] = Wg4[i];

        // a window: s in [j0-63, j0+257), 320 per channel; set row flags
        for (int i = tid; i < 32 * 320; i += 128) {
            int c  = i / 320;
            int si = i - c * 320;
            int s  = j0 - 63 + si;
            float v = 0.0f;
            if (s >= 0 && s < SS)
                v = hshrink(g_u[(b * CC + c0 + c) * SS + s]);
            As[i] = v;
            if (v != 0.0f) flags[c] = 1;   // benign race, all writers store 1
        }
        __syncthreads();

        for (int c = 0; c < 32; c++) {
            if (!flags[c]) continue;       // all-zero row: exact +0, skip
            const float* arowA = As + c * 320 + tid;
            const float* arowB = arowA + 128;
            const float* wrow  = Ws + c * KK;
            #pragma unroll 8
            for (int d = 63; d >= 0; d--) {   // kk ascending
                ulonglong2 wv = *(const ulonglong2*)&wrow[4 * d];
                float aA = arowA[63 - d];
                float aB = arowB[63 - d];
                unsigned long long aA2 = splat2(aA);
                unsigned long long aB2 = splat2(aB);
                fma2(accA0, aA2, wv.x);
                fma2(accA1, aA2, wv.y);
                fma2(accB0, aB2, wv.x);
                fma2(accB1, aB2, wv.y);
            }
        }
    }

    float* outp = g_recon + b * LL;
    {
        float2 p0 = unpack2(accA0);
        float2 p1 = unpack2(accA1);
        *(float4*)&outp[4 * jA] = make_float4(p0.x, p0.y, p1.x, p1.y);
    }
    if (jB < NJ) {
        float2 p0 = unpack2(accB0);
        float2 p1 = unpack2(accB1);
        *(float4*)&outp[4 * jB] = make_float4(p0.x, p0.y, p1.x, p1.y);
    }
}

// ---------------------------------------------------------------------------
// k_out: final a = hardshrink(u), vectorized.
// ---------------------------------------------------------------------------
__global__ __launch_bounds__(256) void k_out(float* __restrict__ out) {
    const int n4 = (BB * CC * SS) / 4;   // 2,015,744
    int i = blockIdx.x * blockDim.x + threadIdx.x;
    if (i < n4) {
        float4 u = ((const float4*)g_u)[i];
        float4 r;
        r.x = hshrink(u.x);
        r.y = hshrink(u.y);
        r.z = hshrink(u.z);
        r.w = hshrink(u.w);
        ((float4*)out)[i] = r;
    }
}

extern "C" void kernel_launch(void* const* d_in, const int* in_sizes, int n_in,
                              void* d_out, int out_size) {
    const float* x = (const float*)d_in[0];   // [16,1,16000]
    const float* W = (const float*)d_in[1];   // [128,1,256]
    float* out = (float*)d_out;               // [16,128,3937]

    const int recon_smem = (32 * KK + 32 * 320 + 32) * (int)sizeof(float); // 73856
    cudaFuncSetAttribute(k_recon, cudaFuncAttributeMaxDynamicSharedMemorySize,
                         recon_smem);

    dim3 gconv(31, 4, BB);
    dim3 grecon(16, BB);

    // Iteration 1: u0 = 0 -> a = 0 -> feedback = 0 -> u1 = 0.1f * drive
    k_conv<0><<<gconv, 256>>>(x, W);

    // Iterations 2..10
    for (int it = 1; it < NITER; it++) {
        k_recon<<<grecon, 128, recon_smem>>>(W);
        k_conv<1><<<gconv, 256>>>(x, W);
    }

    // Final spikegram
    const int n4 = (BB * CC * SS) / 4;
    k_out<<<(n4 + 255) / 256, 256>>>(out);
}

// round 8
// speedup vs baseline: 1.0248x; 1.0248x over previous
#include <cuda_runtime.h>
#include <math.h>

// Problem constants (match reference)
#define BB   16
#define CC   128
#define LL   16000
#define KK   256
#define SS   3937          // (L - K)/4 + 1
#define NITER 10
#define STEP 0.1f
#define THR  0.5f
#define NJ   4000          // recon phase length: L/4

// Scratch (no allocations allowed -> __device__ globals)
__device__ float g_drive[BB * CC * SS];   // ~32.25 MB
__device__ float g_u[BB * CC * SS];       // ~32.25 MB
__device__ float g_recon[BB * LL];        // 1 MB, single-rounded fp32 recon

__device__ __forceinline__ float hshrink(float u) {
    return (fabsf(u) > THR) ? u : 0.0f;
}

// Packed fp32x2 helpers (Blackwell). Each half is an IEEE fp32 FMA -> the
// per-element accumulation chains are bit-identical to scalar FFMA.
__device__ __forceinline__ unsigned long long splat2(float a) {
    unsigned long long r;
    asm("mov.b64 %0, {%1, %1};" : "=l"(r) : "f"(a));
    return r;
}
__device__ __forceinline__ void fma2(unsigned long long& acc,
                                     unsigned long long a,
                                     unsigned long long b) {
    asm("fma.rn.f32x2 %0, %1, %2, %0;" : "+l"(acc) : "l"(a), "l"(b));
}
__device__ __forceinline__ float2 unpack2(unsigned long long v) {
    float lo, hi;
    asm("mov.b64 {%0, %1}, %2;" : "=f"(lo), "=f"(hi) : "l"(v));
    return make_float2(lo, hi);
}

// ---------------------------------------------------------------------------
// k_conv: strided conv (stride 4, K=256), fp32, k-ascending serial FMA chains
// (verified anchor - unchanged since R5). MODE 0: input = x, writes drive and
// u1 = 0.1f*drive. MODE 1: input = g_recon, fused LCA u-update.
// ---------------------------------------------------------------------------
template <int MODE>
__global__ __launch_bounds__(256) void k_conv(const float* __restrict__ xin,
                                              const float* __restrict__ Wg) {
    __shared__ float Ws[32 * KK];    // 32 KB
    __shared__ float xs[768];        // 3 KB

    const int stile = blockIdx.x;    // 0..30
    const int cb    = blockIdx.y;    // 0..3
    const int b     = blockIdx.z;    // 0..15
    const int s0    = stile * 128;
    const int c0    = cb * 32;
    const int tid   = threadIdx.x;

    const float4* Wg4 = (const float4*)(Wg + c0 * KK);
    float4* Ws4 = (float4*)Ws;
    #pragma unroll
    for (int i = tid; i < (32 * KK) / 4; i += 256) Ws4[i] = Wg4[i];

    {
        const float* src = (MODE == 0) ? (xin + b * LL) : (g_recon + b * LL);
        for (int i = tid; i < 768; i += 256) {
            int gt = 4 * s0 + i;
            xs[i] = (gt < LL) ? src[gt] : 0.0f;
        }
    }
    __syncthreads();

    const int lane = tid & 31;
    const int wg   = tid >> 5;

    float acc[4][4];
    #pragma unroll
    for (int i = 0; i < 4; i++)
        #pragma unroll
        for (int j = 0; j < 4; j++) acc[i][j] = 0.0f;

    const float* wrow = Ws + (wg * 4) * KK;

    #pragma unroll 4
    for (int k = 0; k < KK; k += 4) {
        float4 wv0 = *(const float4*)&wrow[0 * KK + k];
        float4 wv1 = *(const float4*)&wrow[1 * KK + k];
        float4 wv2 = *(const float4*)&wrow[2 * KK + k];
        float4 wv3 = *(const float4*)&wrow[3 * KK + k];
        #pragma unroll
        for (int m = 0; m < 4; m++) {
            float4 xv = *(const float4*)&xs[4 * lane + 128 * m + k];
            acc[0][m] += wv0.x * xv.x; acc[0][m] += wv0.y * xv.y;
            acc[0][m] += wv0.z * xv.z; acc[0][m] += wv0.w * xv.w;
            acc[1][m] += wv1.x * xv.x; acc[1][m] += wv1.y * xv.y;
            acc[1][m] += wv1.z * xv.z; acc[1][m] += wv1.w * xv.w;
            acc[2][m] += wv2.x * xv.x; acc[2][m] += wv2.y * xv.y;
            acc[2][m] += wv2.z * xv.z; acc[2][m] += wv2.w * xv.w;
            acc[3][m] += wv3.x * xv.x; acc[3][m] += wv3.y * xv.y;
            acc[3][m] += wv3.z * xv.z; acc[3][m] += wv3.w * xv.w;
        }
    }

    #pragma unroll
    for (int ci = 0; ci < 4; ci++) {
        const int c = c0 + wg * 4 + ci;
        #pragma unroll
        for (int m = 0; m < 4; m++) {
            const int s = s0 + lane + 32 * m;
            if (s < SS) {
                const int idx = (b * CC + c) * SS + s;
                if (MODE == 0) {
                    g_drive[idx] = acc[ci][m];
                    g_u[idx]     = STEP * acc[ci][m];
                } else {
                    float u = g_u[idx];
                    float a = hshrink(u);
                    float t = ((g_drive[idx] - u) - acc[ci][m]) + a;
                    g_u[idx] = fmaf(STEP, t, u);
                }
            }
        }
    }
}

// ---------------------------------------------------------------------------
// k_recon v3: EXACT R5 occupancy shape (256 threads, 1 j per thread, j-tile
// 256, grid (16,16)), same serial chain (c = 0..127 outer ascending,
// d = 63..0 inner). Two bit-exact levers kept from R6:
//   1. packed fma.rn.f32x2: accs (r0,r1) and (r2,r3) as u64; halves FMA
//      issue slots, wavefronts unchanged.
//   2. skip channels whose whole a-window is zero (contributes exactly +0).
// ---------------------------------------------------------------------------
__global__ __launch_bounds__(256) void k_recon(const float* __restrict__ Wg) {
    extern __shared__ float sm[];
    float* Ws = sm;                       // 32*256 floats (32 KB)
    float* As = sm + 32 * KK;             // 32*320 floats (40 KB)
    int* flags = (int*)(sm + 32 * KK + 32 * 320);   // 32 ints

    const int jt  = blockIdx.x;   // 0..15
    const int b   = blockIdx.y;   // 0..15
    const int j0  = jt * 256;
    const int tid = threadIdx.x;  // 0..255
    const int j   = j0 + tid;

    unsigned long long acc0 = 0ULL;   // (r0, r1)
    unsigned long long acc1 = 0ULL;   // (r2, r3)

    for (int cc = 0; cc < 4; cc++) {
        const int c0 = cc * 32;
        __syncthreads();               // previous chunk fully consumed
        if (tid < 32) flags[tid] = 0;
        __syncthreads();

        // W chunk [c0, c0+32)
        const float4* Wg4 = (const float4*)(Wg + c0 * KK);
        float4* Ws4 = (float4*)Ws;
        #pragma unroll
        for (int i = tid; i < (32 * KK) / 4; i += 256) Ws4[i] = Wg4[i];

        // a window: s in [j0-63, j0+257), 320 per channel; set row flags
        for (int i = tid; i < 32 * 320; i += 256) {
            int c  = i / 320;
            int si = i - c * 320;
            int s  = j0 - 63 + si;
            float v = 0.0f;
            if (s >= 0 && s < SS)
                v = hshrink(g_u[(b * CC + c0 + c) * SS + s]);
            As[i] = v;
            if (v != 0.0f) flags[c] = 1;   // benign race, all writers store 1
        }
        __syncthreads();

        for (int c = 0; c < 32; c++) {
            if (!flags[c]) continue;       // all-zero row: exact +0, skip
            const float* arow = As + c * 320 + tid;   // +(63-d) -> a[j-d]
            const float* wrow = Ws + c * KK;
            #pragma unroll 16
            for (int d = 63; d >= 0; d--) {   // kk ascending
                ulonglong2 wv = *(const ulonglong2*)&wrow[4 * d];
                unsigned long long a2 = splat2(arow[63 - d]);
                fma2(acc0, a2, wv.x);
                fma2(acc1, a2, wv.y);
            }
        }
    }

    if (j < NJ) {
        float2 p0 = unpack2(acc0);
        float2 p1 = unpack2(acc1);
        *(float4*)&g_recon[b * LL + 4 * j] = make_float4(p0.x, p0.y, p1.x, p1.y);
    }
}

// ---------------------------------------------------------------------------
// k_out: final a = hardshrink(u), vectorized.
// ---------------------------------------------------------------------------
__global__ __launch_bounds__(256) void k_out(float* __restrict__ out) {
    const int n4 = (BB * CC * SS) / 4;   // 2,015,744
    int i = blockIdx.x * blockDim.x + threadIdx.x;
    if (i < n4) {
        float4 u = ((const float4*)g_u)[i];
        float4 r;
        r.x = hshrink(u.x);
        r.y = hshrink(u.y);
        r.z = hshrink(u.z);
        r.w = hshrink(u.w);
        ((float4*)out)[i] = r;
    }
}

extern "C" void kernel_launch(void* const* d_in, const int* in_sizes, int n_in,
                              void* d_out, int out_size) {
    const float* x = (const float*)d_in[0];   // [16,1,16000]
    const float* W = (const float*)d_in[1];   // [128,1,256]
    float* out = (float*)d_out;               // [16,128,3937]

    const int recon_smem = (32 * KK + 32 * 320 + 32) * (int)sizeof(float); // 73856
    cudaFuncSetAttribute(k_recon, cudaFuncAttributeMaxDynamicSharedMemorySize,
                         recon_smem);

    dim3 gconv(31, 4, BB);
    dim3 grecon(16, BB);

    // Iteration 1: u0 = 0 -> a = 0 -> feedback = 0 -> u1 = 0.1f * drive
    k_conv<0><<<gconv, 256>>>(x, W);

    // Iterations 2..10
    for (int it = 1; it < NITER; it++) {
        k_recon<<<grecon, 256, recon_smem>>>(W);
        k_conv<1><<<gconv, 256>>>(x, W);
    }

    // Final spikegram
    const int n4 = (BB * CC * SS) / 4;
    k_out<<<(n4 + 255) / 256, 256>>>(out);
}